// round 1
// baseline (speedup 1.0000x reference)
#include <cuda_runtime.h>

// FilteringActLayer: bias -> 2x zero-insert upsample + 12-tap separable FIR
// -> leakyReLU*gain, clamp -> 12-tap separable FIR + 2x downsample.
// Filters are symmetric (firwin), so correlation == convolution.
//
// Fully fused per-tile kernel. Output tile 32x32 per (n,c) plane.
// Polyphase upsample: 6 taps per output parity.
//   u[i] = sum_d tapsU[i&1][d] * x[(i>>1 - 5 + d)]   (global indexing)
// with tapsU[0][d] = 2*up[2d+1] (even i), tapsU[1][d] = 2*up[2d] (odd i).
// Downsample: y[o] = sum_k fd[k] * a[2o+k].

#define TS   32          // output tile side
#define XS   42          // input patch side  (TS + 10)
#define US   74          // upsampled patch side (2*TS + 10)

__global__ __launch_bounds__(256, 5)
void filt_act_kernel(const float* __restrict__ x,
                     const float* __restrict__ b,
                     const float* __restrict__ upf,
                     const float* __restrict__ dnf,
                     const float* __restrict__ gainp,
                     const float* __restrict__ slopep,
                     const float* __restrict__ clampp,
                     float* __restrict__ out)
{
    // bufA holds xs (42*42=1764) during stages 0-1, then v (32*74=2368) in stage 3.
    __shared__ float bufA[TS * US];          // 2368 floats
    __shared__ float t1[US * XS];            // 74*42 = 3108
    __shared__ float a [US * US];            // 74*74 = 5476
    __shared__ float tU[2][6];
    __shared__ float tD[12];
    __shared__ float s_bias, s_gain, s_slope, s_clamp;

    const int tid   = threadIdx.x;
    const int plane = blockIdx.z;            // n*128 + c
    const int c     = plane & 127;
    const int R0    = blockIdx.y * TS;
    const int C0    = blockIdx.x * TS;
    const float* __restrict__ xp = x   + (size_t)plane * 128 * 128;
    float*       __restrict__ op = out + (size_t)plane * 128 * 128;

    if (tid < 6)        tU[0][tid]      = 2.0f * upf[2 * tid + 1];
    else if (tid < 12)  tU[1][tid - 6]  = 2.0f * upf[2 * (tid - 6)];
    else if (tid < 24)  tD[tid - 12]    = dnf[tid - 12];
    else if (tid == 24) {
        s_bias  = b[c];
        s_gain  = *gainp;
        s_slope = *slopep;
        s_clamp = *clampp;
    }
    __syncthreads();

    const float bias  = s_bias;
    const float gain  = s_gain;
    const float slope = s_slope;
    const float clmp  = s_clamp;

    // ---- stage 0: load input patch (with +bias, zero pad outside) ----
    float* xs = bufA;
    #pragma unroll 2
    for (int idx = tid; idx < XS * XS; idx += 256) {
        int r  = idx / XS;
        int cc = idx - r * XS;
        int gr = R0 - 5 + r;
        int gc = C0 - 5 + cc;
        float v = 0.0f;
        if ((unsigned)gr < 128u && (unsigned)gc < 128u)
            v = xp[gr * 128 + gc] + bias;
        xs[idx] = v;
    }
    __syncthreads();

    // ---- stage 1: upsample along H (polyphase, 6 taps) ----
    // t1[i][cc] = sum_d tU[i&1][d] * xs[(i>>1)+d][cc]
    #pragma unroll 2
    for (int idx = tid; idx < US * XS; idx += 256) {
        int i  = idx / XS;
        int cc = idx - i * XS;
        const float* tp = tU[i & 1];
        int j0 = i >> 1;
        float s = 0.0f;
        #pragma unroll
        for (int d = 0; d < 6; d++)
            s = fmaf(tp[d], xs[(j0 + d) * XS + cc], s);
        t1[idx] = s;
    }
    __syncthreads();

    // ---- stage 2: upsample along W (6 taps) + activation ----
    #pragma unroll 2
    for (int idx = tid; idx < US * US; idx += 256) {
        int i = idx / US;
        int w = idx - i * US;
        const float* tp  = tU[w & 1];
        const float* row = &t1[i * XS + (w >> 1)];
        float s = 0.0f;
        #pragma unroll
        for (int d = 0; d < 6; d++)
            s = fmaf(tp[d], row[d], s);
        // leaky relu * gain, clamp
        s = (s >= 0.0f ? s : s * slope) * gain;
        s = fminf(fmaxf(s, -clmp), clmp);
        a[idx] = s;
    }
    __syncthreads();

    // ---- stage 3: downsample along H (12 taps, stride 2) ----
    float* v = bufA;   // xs is dead now
    #pragma unroll 2
    for (int idx = tid; idx < TS * US; idx += 256) {
        int o = idx / US;
        int w = idx - o * US;
        const float* col = &a[(2 * o) * US + w];
        float s = 0.0f;
        #pragma unroll
        for (int k = 0; k < 12; k++)
            s = fmaf(tD[k], col[k * US], s);
        v[idx] = s;
    }
    __syncthreads();

    // ---- stage 4: downsample along W (12 taps, stride 2) + store ----
    #pragma unroll 2
    for (int idx = tid; idx < TS * TS; idx += 256) {
        int o = idx >> 5;
        int w = idx & 31;
        const float* row = &v[o * US + 2 * w];
        float s = 0.0f;
        #pragma unroll
        for (int k = 0; k < 12; k++)
            s = fmaf(tD[k], row[k], s);
        op[(R0 + o) * 128 + (C0 + w)] = s;
    }
}

extern "C" void kernel_launch(void* const* d_in, const int* in_sizes, int n_in,
                              void* d_out, int out_size)
{
    const float* x    = (const float*)d_in[0];
    const float* b    = (const float*)d_in[1];
    const float* upf  = (const float*)d_in[2];
    const float* dnf  = (const float*)d_in[3];
    const float* gain = (const float*)d_in[4];
    const float* slope= (const float*)d_in[5];
    const float* clmp = (const float*)d_in[6];
    float* out = (float*)d_out;

    dim3 grid(128 / TS, 128 / TS, 8 * 128);   // (4,4,1024)
    filt_act_kernel<<<grid, 256>>>(x, b, upf, dnf, gain, slope, clmp, out);
}

// round 2
// speedup vs baseline: 1.8192x; 1.8192x over previous
#include <cuda_runtime.h>

// FilteringActLayer, fused per-tile, quad register blocking per stage.
// bias -> x2 polyphase upsample (6-tap per parity) H,W -> lrelu*gain,clamp
// -> 12-tap FIR + /2 downsample H,W.
//
// Tile: 32x32 outputs per (n,c) plane. Patches:
//   xs 42x42 (stride 43, 44 rows alloc) -> t1 74x42 (stride 45) ->
//   a 74x74 (stride 75) -> v 32x74 (stride 75, aliases xs) -> out 32x32.
// Strides odd => conflict-free LDS for the lane patterns used.

#define TS 32

__global__ __launch_bounds__(256, 4)
void filt_act_kernel(const float* __restrict__ x,
                     const float* __restrict__ b,
                     const float* __restrict__ upf,
                     const float* __restrict__ dnf,
                     const float* __restrict__ gainp,
                     const float* __restrict__ slopep,
                     const float* __restrict__ clampp,
                     float* __restrict__ out)
{
    __shared__ float bufA[2400];        // xs: 44*43=1892  |  v: 32*75=2400
    __shared__ float t1[74 * 45];       // 3330
    __shared__ float a [74 * 75];       // 5550
    __shared__ float sU0[6], sU1[6], sD[12];
    __shared__ float sPar[4];           // bias, gain, slope, clamp

    const int tid   = threadIdx.x;
    const int plane = blockIdx.z;                  // n*128 + c
    const int R0    = blockIdx.y * TS;
    const int C0    = blockIdx.x * TS;
    const float* __restrict__ xp = x   + (size_t)plane * 128 * 128;
    float*       __restrict__ op = out + (size_t)plane * 128 * 128;

    if (tid < 6)        sU0[tid]     = 2.0f * upf[2 * tid + 1];   // even parity
    else if (tid < 12)  sU1[tid - 6] = 2.0f * upf[2 * (tid - 6)]; // odd parity
    else if (tid < 24)  sD[tid - 12] = dnf[tid - 12];
    else if (tid == 24) {
        sPar[0] = b[plane & 127];
        sPar[1] = *gainp;
        sPar[2] = *slopep;
        sPar[3] = *clampp;
    }

    // ---- stage 0: load 42x42 input patch (+bias, zero outside) ----
    float* xs = bufA;
    __syncthreads();
    const float bias  = sPar[0];
    const float gain  = sPar[1];
    const float slope = sPar[2];
    const float clmp  = sPar[3];

    #pragma unroll
    for (int it = 0; it < 7; it++) {
        int idx = tid + it * 256;
        if (idx < 1764) {
            int r  = idx / 42;
            int cc = idx - r * 42;
            int gr = R0 - 5 + r;
            int gc = C0 - 5 + cc;
            float v = 0.0f;
            if ((unsigned)gr < 128u && (unsigned)gc < 128u)
                v = xp[gr * 128 + gc] + bias;
            xs[r * 43 + cc] = v;
        }
    }
    __syncthreads();

    // hoist upsample taps into registers
    float u0[6], u1[6];
    #pragma unroll
    for (int d = 0; d < 6; d++) { u0[d] = sU0[d]; u1[d] = sU1[d]; }

    // ---- stage 1: upsample H. items = 42 cols x 19 j0-pairs = 798 ----
    // t1[2j0+s][cc], s<4, from xs[j0..j0+7][cc]
    #pragma unroll
    for (int it = 0; it < 4; it++) {
        int idx = tid + it * 256;
        if (idx < 798) {
            int j0p = idx / 42;
            int cc  = idx - j0p * 42;
            int j0  = 2 * j0p;
            const float* p = &xs[j0 * 43 + cc];
            float w[8];
            #pragma unroll
            for (int d = 0; d < 8; d++) w[d] = p[d * 43];
            float o0 = 0.f, o1 = 0.f, o2 = 0.f, o3 = 0.f;
            #pragma unroll
            for (int d = 0; d < 6; d++) {
                o0 = fmaf(u0[d], w[d],     o0);
                o1 = fmaf(u1[d], w[d],     o1);
                o2 = fmaf(u0[d], w[d + 1], o2);
                o3 = fmaf(u1[d], w[d + 1], o3);
            }
            float* q = &t1[(2 * j0) * 45 + cc];
            q[0]  = o0;
            q[45] = o1;
            if (j0p < 18) { q[90] = o2; q[135] = o3; }
        }
    }
    __syncthreads();

    // ---- stage 2: upsample W + activation. items = 74 rows x 19 = 1406 ----
    #pragma unroll
    for (int it = 0; it < 6; it++) {
        int idx = tid + it * 256;
        if (idx < 1406) {
            int j0p = idx / 74;
            int i   = idx - j0p * 74;
            int j0  = 2 * j0p;
            const float* p = &t1[i * 45 + j0];
            float w[8];
            #pragma unroll
            for (int d = 0; d < 8; d++) w[d] = p[d];
            float o0 = 0.f, o1 = 0.f, o2 = 0.f, o3 = 0.f;
            #pragma unroll
            for (int d = 0; d < 6; d++) {
                o0 = fmaf(u0[d], w[d],     o0);
                o1 = fmaf(u1[d], w[d],     o1);
                o2 = fmaf(u0[d], w[d + 1], o2);
                o3 = fmaf(u1[d], w[d + 1], o3);
            }
            // activation
            o0 = (o0 >= 0.f ? o0 : o0 * slope) * gain;
            o1 = (o1 >= 0.f ? o1 : o1 * slope) * gain;
            o2 = (o2 >= 0.f ? o2 : o2 * slope) * gain;
            o3 = (o3 >= 0.f ? o3 : o3 * slope) * gain;
            o0 = fminf(fmaxf(o0, -clmp), clmp);
            o1 = fminf(fmaxf(o1, -clmp), clmp);
            o2 = fminf(fmaxf(o2, -clmp), clmp);
            o3 = fminf(fmaxf(o3, -clmp), clmp);
            float* q = &a[i * 75 + 2 * j0];
            q[0] = o0;
            q[1] = o1;
            if (j0p < 18) { q[2] = o2; q[3] = o3; }
        }
    }
    __syncthreads();

    // hoist down taps
    float fd[12];
    #pragma unroll
    for (int k = 0; k < 12; k++) fd[k] = sD[k];

    // ---- stage 3: downsample H. items = 74 cols x 8 o-quads = 592 ----
    float* v = bufA;    // xs dead
    #pragma unroll
    for (int it = 0; it < 3; it++) {
        int idx = tid + it * 256;
        if (idx < 592) {
            int q4 = idx / 74;
            int w  = idx - q4 * 74;
            const float* p = &a[(8 * q4) * 75 + w];
            float r[18];
            #pragma unroll
            for (int k = 0; k < 18; k++) r[k] = p[k * 75];
            float o0 = 0.f, o1 = 0.f, o2 = 0.f, o3 = 0.f;
            #pragma unroll
            for (int k = 0; k < 12; k++) {
                o0 = fmaf(fd[k], r[k],     o0);
                o1 = fmaf(fd[k], r[k + 2], o1);
                o2 = fmaf(fd[k], r[k + 4], o2);
                o3 = fmaf(fd[k], r[k + 6], o3);
            }
            float* q = &v[(4 * q4) * 75 + w];
            q[0]   = o0;
            q[75]  = o1;
            q[150] = o2;
            q[225] = o3;
        }
    }
    __syncthreads();

    // ---- stage 4: downsample W + store. items = 32 rows x 8 w-quads = 256 ----
    {
        int o  = tid >> 3;
        int q  = tid & 7;
        const float* p = &v[o * 75 + 8 * q];
        float r[18];
        #pragma unroll
        for (int k = 0; k < 18; k++) r[k] = p[k];
        float o0 = 0.f, o1 = 0.f, o2 = 0.f, o3 = 0.f;
        #pragma unroll
        for (int k = 0; k < 12; k++) {
            o0 = fmaf(fd[k], r[k],     o0);
            o1 = fmaf(fd[k], r[k + 2], o1);
            o2 = fmaf(fd[k], r[k + 4], o2);
            o3 = fmaf(fd[k], r[k + 6], o3);
        }
        float4 st = make_float4(o0, o1, o2, o3);
        *reinterpret_cast<float4*>(&op[(R0 + o) * 128 + C0 + 4 * q]) = st;
    }
}

extern "C" void kernel_launch(void* const* d_in, const int* in_sizes, int n_in,
                              void* d_out, int out_size)
{
    const float* x     = (const float*)d_in[0];
    const float* b     = (const float*)d_in[1];
    const float* upf   = (const float*)d_in[2];
    const float* dnf   = (const float*)d_in[3];
    const float* gain  = (const float*)d_in[4];
    const float* slope = (const float*)d_in[5];
    const float* clmp  = (const float*)d_in[6];
    float* out = (float*)d_out;

    dim3 grid(128 / TS, 128 / TS, 8 * 128);   // (4,4,1024)
    filt_act_kernel<<<grid, 256>>>(x, b, upf, dnf, gain, slope, clmp, out);
}

// round 3
// speedup vs baseline: 2.0966x; 1.1525x over previous
#include <cuda_runtime.h>

// FilteringActLayer fused per-tile kernel, v3: sliding-window register
// streaming in every FIR stage to minimize shared-memory traffic.
// bias -> x2 polyphase upsample (6-tap/parity) H,W -> lrelu*gain,clamp
// -> 12-tap FIR + /2 downsample H,W.  Output tile 32x32 per (n,c) plane.
//
// Buffers (floats):
//   xs 44x42 (stride 43) in bufA -> t1 74x42 (stride 45) ->
//   a 74x74 (stride 75) -> v 32x74 (stride 75, aliases bufA) -> out.
// All odd strides => conflict-free cross-lane LDS patterns.

#define TS 32

__global__ __launch_bounds__(256, 4)
void filt_act_kernel(const float* __restrict__ x,
                     const float* __restrict__ b,
                     const float* __restrict__ upf,
                     const float* __restrict__ dnf,
                     const float* __restrict__ gainp,
                     const float* __restrict__ slopep,
                     const float* __restrict__ clampp,
                     float* __restrict__ out)
{
    __shared__ float bufA[2400];          // xs: 45*43 fits w/ slack | v: 32*75=2400
    __shared__ float t1[74 * 45 + 8];     // +8 pad: tail-window overreads
    __shared__ float a [74 * 75];
    __shared__ float sU0[6], sU1[6], sD[12], sPar[4];

    const int tid   = threadIdx.x;
    const int plane = blockIdx.z;                  // n*128 + c
    const int R0    = blockIdx.y * TS;
    const int C0    = blockIdx.x * TS;
    const float* __restrict__ xp = x   + (size_t)plane * 128 * 128;
    float*       __restrict__ op = out + (size_t)plane * 128 * 128;

    if (tid < 6)        sU0[tid]     = 2.0f * upf[2 * tid + 1];   // even parity
    else if (tid < 12)  sU1[tid - 6] = 2.0f * upf[2 * (tid - 6)]; // odd parity
    else if (tid < 24)  sD[tid - 12] = dnf[tid - 12];
    else if (tid == 24) {
        sPar[0] = b[plane & 127];
        sPar[1] = *gainp;
        sPar[2] = *slopep;
        sPar[3] = *clampp;
    }
    __syncthreads();

    const float bias  = sPar[0];
    const float gain  = sPar[1];
    const float slope = sPar[2];
    const float clmp  = sPar[3];

    // ---- stage 0: load 44x42 input patch (+bias, zero outside) ----
    // rows 42,43 only feed discarded lanes of S1's tail group but must be
    // defined; same guard handles them.
    float* xs = bufA;
    #pragma unroll
    for (int it = 0; it < 8; it++) {
        int idx = tid + it * 256;
        if (idx < 1848) {                         // 44*42
            int r  = idx / 42;
            int cc = idx - r * 42;
            int gr = R0 - 5 + r;
            int gc = C0 - 5 + cc;
            float v = 0.0f;
            if ((unsigned)gr < 128u && (unsigned)gc < 128u)
                v = xp[gr * 128 + gc] + bias;
            xs[r * 43 + cc] = v;
        }
    }
    __syncthreads();

    float u0[6], u1[6];
    #pragma unroll
    for (int d = 0; d < 6; d++) { u0[d] = sU0[d]; u1[d] = sU1[d]; }

    // ---- stage 1: upsample H. 210 threads: col cc, chunk of 4 j0p each ----
    // j0p -> output rows 4*j0p..+3 from xs rows 2*j0p..2*j0p+6.
    if (tid < 210) {
        int g  = tid / 42;              // 0..4, j0p = 4g..4g+3
        int cc = tid - 42 * g;
        const float* p = &xs[(8 * g) * 43 + cc];
        float w[13];
        #pragma unroll
        for (int d = 0; d < 13; d++) w[d] = p[d * 43];
        #pragma unroll
        for (int s = 0; s < 4; s++) {
            int row0 = 16 * g + 4 * s;           // = 4*j0p
            float o0 = 0.f, o1 = 0.f, o2 = 0.f, o3 = 0.f;
            #pragma unroll
            for (int d = 0; d < 6; d++) {
                float wa = w[2 * s + d], wb = w[2 * s + d + 1];
                o0 = fmaf(u0[d], wa, o0);
                o1 = fmaf(u1[d], wa, o1);
                o2 = fmaf(u0[d], wb, o2);
                o3 = fmaf(u1[d], wb, o3);
            }
            float* q = &t1[row0 * 45 + cc];
            if (row0 < 74)     q[0]   = o0;
            if (row0 + 1 < 74) q[45]  = o1;
            if (row0 + 2 < 74) q[90]  = o2;
            if (row0 + 3 < 74) q[135] = o3;
        }
    }
    __syncthreads();

    // ---- stage 2: upsample W + act. 222 threads: row i, chunk of 7 j0p ----
    if (tid < 222) {
        int i = tid % 74;
        int g = tid / 74;               // 0..2, j0p = 7g..7g+6
        const float* p = &t1[i * 45 + 14 * g];
        float w[19];
        #pragma unroll
        for (int d = 0; d < 19; d++) w[d] = p[d];
        float* qrow = &a[i * 75];
        #pragma unroll
        for (int t = 0; t < 7; t++) {
            int j0p = 7 * g + t;
            if (j0p < 19) {
                float o0 = 0.f, o1 = 0.f, o2 = 0.f, o3 = 0.f;
                #pragma unroll
                for (int d = 0; d < 6; d++) {
                    float wa = w[2 * t + d], wb = w[2 * t + d + 1];
                    o0 = fmaf(u0[d], wa, o0);
                    o1 = fmaf(u1[d], wa, o1);
                    o2 = fmaf(u0[d], wb, o2);
                    o3 = fmaf(u1[d], wb, o3);
                }
                o0 = (o0 >= 0.f ? o0 : o0 * slope) * gain;
                o1 = (o1 >= 0.f ? o1 : o1 * slope) * gain;
                o2 = (o2 >= 0.f ? o2 : o2 * slope) * gain;
                o3 = (o3 >= 0.f ? o3 : o3 * slope) * gain;
                o0 = fminf(fmaxf(o0, -clmp), clmp);
                o1 = fminf(fmaxf(o1, -clmp), clmp);
                o2 = fminf(fmaxf(o2, -clmp), clmp);
                o3 = fminf(fmaxf(o3, -clmp), clmp);
                float* q = &qrow[4 * j0p];
                q[0] = o0;
                q[1] = o1;
                if (j0p < 18) { q[2] = o2; q[3] = o3; }
            }
        }
    }
    __syncthreads();

    float fd[12];
    #pragma unroll
    for (int k = 0; k < 12; k++) fd[k] = sD[k];

    // ---- stage 3: downsample H. 222 threads: col w, ring of 12, walk o ----
    float* v = bufA;   // xs dead
    if (tid < 222) {
        int ww = tid % 74;
        int g  = tid / 74;              // 0..2, o = 11g + s
        int obase = 11 * g;
        const float* pc = &a[(2 * obase) * 75 + ww];
        float ring[12];
        #pragma unroll
        for (int d = 0; d < 10; d++) ring[d] = pc[d * 75];
        #pragma unroll
        for (int s = 0; s < 11; s++) {
            int o = obase + s;
            if (o < 32) {
                ring[(2 * s + 10) % 12] = pc[(2 * s + 10) * 75];
                ring[(2 * s + 11) % 12] = pc[(2 * s + 11) * 75];
                float acc = 0.f;
                #pragma unroll
                for (int k = 0; k < 12; k++)
                    acc = fmaf(fd[k], ring[(2 * s + k) % 12], acc);
                v[o * 75 + ww] = acc;
            }
        }
    }
    __syncthreads();

    // ---- stage 4: downsample W + store. 128 threads: 8 outputs each ----
    if (tid < 128) {
        int o  = tid >> 2;
        int qq = tid & 3;
        const float* p = &v[o * 75 + 16 * qq];
        float w[26];
        #pragma unroll
        for (int j = 0; j < 26; j++) w[j] = p[j];
        float y[8];
        #pragma unroll
        for (int m = 0; m < 8; m++) {
            float acc = 0.f;
            #pragma unroll
            for (int k = 0; k < 12; k++)
                acc = fmaf(fd[k], w[2 * m + k], acc);
            y[m] = acc;
        }
        float* q = &op[(R0 + o) * 128 + C0 + 8 * qq];
        *reinterpret_cast<float4*>(q)     = make_float4(y[0], y[1], y[2], y[3]);
        *reinterpret_cast<float4*>(q + 4) = make_float4(y[4], y[5], y[6], y[7]);
    }
}

extern "C" void kernel_launch(void* const* d_in, const int* in_sizes, int n_in,
                              void* d_out, int out_size)
{
    const float* x     = (const float*)d_in[0];
    const float* b     = (const float*)d_in[1];
    const float* upf   = (const float*)d_in[2];
    const float* dnf   = (const float*)d_in[3];
    const float* gain  = (const float*)d_in[4];
    const float* slope = (const float*)d_in[5];
    const float* clmp  = (const float*)d_in[6];
    float* out = (float*)d_out;

    dim3 grid(128 / TS, 128 / TS, 8 * 128);   // (4,4,1024)
    filt_act_kernel<<<grid, 256>>>(x, b, upf, dnf, gain, slope, clmp, out);
}